// round 14
// baseline (speedup 1.0000x reference)
#include <cuda_runtime.h>
#include <cuda_bf16.h>
#include <cstdint>

#define B   32
#define T   512
#define MIN 4
#define H   512
#define H2  1024
#define H3  1536
#define H6  3072
#define BT  (B*T)

#define NB  64
#define JS  8

typedef unsigned long long ull;

// ---------------- packed f32x2 helpers ----------------
__device__ __forceinline__ ull fma2(ull a, ull b, ull c) {
    ull d;
    asm("fma.rn.f32x2 %0, %1, %2, %3;" : "=l"(d) : "l"(a), "l"(b), "l"(c));
    return d;
}
__device__ __forceinline__ float lo2(ull v) { return __uint_as_float((unsigned)v); }
__device__ __forceinline__ float hi2(ull v) { return __uint_as_float((unsigned)(v >> 32)); }

// ---------------- cp.async helpers ----------------
__device__ __forceinline__ void cp16(uint32_t smem, const void* gmem) {
    asm volatile("cp.async.cg.shared.global [%0], [%1], 16;" :: "r"(smem), "l"(gmem));
}
__device__ __forceinline__ void cp_commit() {
    asm volatile("cp.async.commit_group;");
}
template <int N>
__device__ __forceinline__ void cp_wait() {
    asm volatile("cp.async.wait_group %0;" :: "n"(N));
}

// ---------------- tensor-core helpers ----------------
__device__ __forceinline__ void ldm_x4(uint32_t* r, uint32_t addr) {
    asm volatile("ldmatrix.sync.aligned.m8n8.x4.shared.b16 {%0,%1,%2,%3}, [%4];"
        : "=r"(r[0]), "=r"(r[1]), "=r"(r[2]), "=r"(r[3]) : "r"(addr));
}
__device__ __forceinline__ void ldm_x4_t(uint32_t* r, uint32_t addr) {
    asm volatile("ldmatrix.sync.aligned.m8n8.x4.trans.shared.b16 {%0,%1,%2,%3}, [%4];"
        : "=r"(r[0]), "=r"(r[1]), "=r"(r[2]), "=r"(r[3]) : "r"(addr));
}
__device__ __forceinline__ void mma_bf16(float* c, const uint32_t* a, const uint32_t* b) {
    asm volatile("mma.sync.aligned.m16n8k16.row.col.f32.bf16.bf16.f32 "
        "{%0,%1,%2,%3}, {%4,%5,%6,%7}, {%8,%9}, {%0,%1,%2,%3};"
        : "+f"(c[0]), "+f"(c[1]), "+f"(c[2]), "+f"(c[3])
        : "r"(a[0]), "r"(a[1]), "r"(a[2]), "r"(a[3]), "r"(b[0]), "r"(b[1]));
}

// ---------------- device scratch ----------------
__device__ __align__(16) __nv_bfloat16 g_embx_hi[BT * H];
__device__ __align__(16) __nv_bfloat16 g_embx_lo[BT * H];
__device__ __align__(16) __nv_bfloat16 g_wxc_hi[(size_t)H * H6];   // [Wx_f | Wx_b]
__device__ __align__(16) __nv_bfloat16 g_wxc_lo[(size_t)H * H6];
__device__ __align__(16) __nv_bfloat16 g_wd_hi[H2 * H];
__device__ __align__(16) __nv_bfloat16 g_wd_lo[H2 * H];
__device__ __align__(16) __nv_bfloat16 g_oc_hi[(size_t)(BT + B) * H2];
__device__ __align__(16) __nv_bfloat16 g_oc_lo[(size_t)(BT + B) * H2];
__device__ float    g_bcat[H6];                 // [b_f_in | b_b_in]
__device__ float    g_gx[(size_t)BT * H6];      // [bt][f 0..1535 | b 1536..3071]
__device__ float    g_hbuf[2][2][B * H];
__device__ unsigned g_grp[2][8][32];            // group counters (128B lines)
__device__ unsigned g_root[2][32];              // root counters

// ---------------- init ----------------
__global__ void init_kernel() {
    int tid = blockIdx.x * blockDim.x + threadIdx.x;
    if (tid < 16) g_grp[tid >> 3][tid & 7][0] = 0;
    if (tid < 2)  g_root[tid][0] = 0;
    for (int i = tid; i < B * H; i += gridDim.x * blockDim.x) {
        g_hbuf[0][0][i] = 0.f;
        g_hbuf[1][0][i] = 0.f;
    }
}

// ---------------- split fp32 -> (hi, lo) bf16, plain ----------------
__global__ void split_kernel(const float* __restrict__ src,
                             __nv_bfloat16* __restrict__ hi,
                             __nv_bfloat16* __restrict__ lo, int n) {
    int i = blockIdx.x * blockDim.x + threadIdx.x;
    if (i < n) {
        float x = src[i];
        __nv_bfloat16 h = __float2bfloat16(x);
        hi[i] = h;
        lo[i] = __float2bfloat16(x - __bfloat162float(h));
    }
}

// ---------------- split into concatenated layout ----------------
__global__ void split_cat_kernel(const float* __restrict__ src,
                                 __nv_bfloat16* __restrict__ hi,
                                 __nv_bfloat16* __restrict__ lo,
                                 int rows, int cols, int ldo, int coloff) {
    int i = blockIdx.x * blockDim.x + threadIdx.x;
    if (i < rows * cols) {
        int r = i / cols;
        int c = i - r * cols;
        float x = src[i];
        __nv_bfloat16 h = __float2bfloat16(x);
        size_t o = (size_t)r * ldo + coloff + c;
        hi[o] = h;
        lo[o] = __float2bfloat16(x - __bfloat162float(h));
    }
}

// ---------------- bias concat ----------------
__global__ void bias_cat_kernel(const float* __restrict__ bf_,
                                const float* __restrict__ bb_) {
    int i = blockIdx.x * blockDim.x + threadIdx.x;
    if (i < H3) {
        g_bcat[i]      = bf_[i];
        g_bcat[H3 + i] = bb_[i];
    }
}

// ---------------- embedding gather + sum -> split bf16 ----------------
__global__ void embed_kernel(const int* __restrict__ seqs,
                             const float* __restrict__ emb) {
    int bt = blockIdx.x;
    int i4 = threadIdx.x * 4;
    const int* s = seqs + bt * MIN;
    float acc[4] = {0.f, 0.f, 0.f, 0.f};
#pragma unroll
    for (int m = 0; m < MIN; m++) {
        size_t row = (size_t)s[m] * H;
        float4 v = *reinterpret_cast<const float4*>(emb + row + i4);
        acc[0] += v.x; acc[1] += v.y; acc[2] += v.z; acc[3] += v.w;
    }
    __nv_bfloat16 hv[4], lv[4];
#pragma unroll
    for (int q = 0; q < 4; q++) {
        hv[q] = __float2bfloat16(acc[q]);
        lv[q] = __float2bfloat16(acc[q] - __bfloat162float(hv[q]));
    }
    size_t o = (size_t)bt * H + i4;
    *reinterpret_cast<ull*>(&g_embx_hi[o]) = *reinterpret_cast<ull*>(hv);
    *reinterpret_cast<ull*>(&g_embx_lo[o]) = *reinterpret_cast<ull*>(lv);
}

// ---------------- split-bf16 tensor-core GEMM (R13, unchanged) ----------------
#define AS_STRIDE 40
#define BS_STRIDE 136
#define AS_BUF (128 * AS_STRIDE)
#define BS_BUF (32 * BS_STRIDE)
#define OFF_AHI 0
#define OFF_ALO (2 * AS_BUF)
#define OFF_BHI (4 * AS_BUF)
#define OFF_BLO (4 * AS_BUF + 2 * BS_BUF)
#define GEMM_SMEM_BYTES (2 * (4 * AS_BUF + 4 * BS_BUF))

__global__ void __launch_bounds__(256, 1) gemm_bf16_kernel(
        const __nv_bfloat16* __restrict__ Ahi, const __nv_bfloat16* __restrict__ Alo,
        const __nv_bfloat16* __restrict__ Bhi, const __nv_bfloat16* __restrict__ Blo,
        const float* __restrict__ bias, float* __restrict__ C,
        int Mr, int N, int K) {
    extern __shared__ __nv_bfloat16 smem_bf[];
    const uint32_t sbase = (uint32_t)__cvta_generic_to_shared(smem_bf);
    const int tid  = threadIdx.x;
    const int lane = tid & 31;
    const int wid  = tid >> 5;
    const int m0 = blockIdx.y * 128;
    const int n0 = blockIdx.x * 128;
    const int wm = (wid & 3) * 32;
    const int wn = (wid >> 2) * 64;

    int aRow[2], aCol[2], bRow[2], bCol[2];
    bool aOk[2];
#pragma unroll
    for (int l = 0; l < 2; l++) {
        int c = tid + l * 256;
        aRow[l] = c >> 2;  aCol[l] = (c & 3) * 8;
        bRow[l] = c >> 4;  bCol[l] = (c & 15) * 8;
        aOk[l] = (m0 + aRow[l]) < Mr;
    }

#define ISSUE_STAGE(KT, P) do {                                                   \
    _Pragma("unroll")                                                             \
    for (int l = 0; l < 2; l++) {                                                 \
        if (aOk[l]) {                                                             \
            size_t go = (size_t)(m0 + aRow[l]) * K + (KT) + aCol[l];              \
            uint32_t so = (uint32_t)((P) * AS_BUF + aRow[l] * AS_STRIDE + aCol[l]); \
            cp16(sbase + 2u * (OFF_AHI + so), Ahi + go);                          \
            cp16(sbase + 2u * (OFF_ALO + so), Alo + go);                          \
        }                                                                         \
        {                                                                         \
            size_t go = (size_t)((KT) + bRow[l]) * N + n0 + bCol[l];              \
            uint32_t so = (uint32_t)((P) * BS_BUF + bRow[l] * BS_STRIDE + bCol[l]); \
            cp16(sbase + 2u * (OFF_BHI + so), Bhi + go);                          \
            cp16(sbase + 2u * (OFF_BLO + so), Blo + go);                          \
        }                                                                         \
    }                                                                             \
    cp_commit();                                                                  \
} while (0)

    float cfr[2][8][4];
#pragma unroll
    for (int i = 0; i < 2; i++)
#pragma unroll
        for (int j = 0; j < 8; j++)
#pragma unroll
            for (int q = 0; q < 4; q++) cfr[i][j][q] = 0.f;

    ISSUE_STAGE(0, 0);
    int p = 0;
    for (int kt = 0; kt < K; kt += 32) {
        const bool more = (kt + 32) < K;
        if (more) { ISSUE_STAGE(kt + 32, p ^ 1); cp_wait<1>(); }
        else      { cp_wait<0>(); }
        __syncthreads();

#pragma unroll
        for (int kk = 0; kk < 2; kk++) {
            uint32_t ah[2][4], al[2][4];
#pragma unroll
            for (int i = 0; i < 2; i++) {
                int r  = wm + i * 16 + (lane & 15);
                int cc = kk * 16 + ((lane >> 4) << 3);
                uint32_t ao = (uint32_t)(p * AS_BUF + r * AS_STRIDE + cc);
                ldm_x4(ah[i], sbase + 2u * (OFF_AHI + ao));
                ldm_x4(al[i], sbase + 2u * (OFF_ALO + ao));
            }
            uint32_t bh[4][4], bl[4][4];
#pragma unroll
            for (int j2 = 0; j2 < 4; j2++) {
                int kr = kk * 16 + (lane & 15);
                int nc = wn + j2 * 16 + ((lane >> 4) << 3);
                uint32_t bo = (uint32_t)(p * BS_BUF + kr * BS_STRIDE + nc);
                ldm_x4_t(bh[j2], sbase + 2u * (OFF_BHI + bo));
                ldm_x4_t(bl[j2], sbase + 2u * (OFF_BLO + bo));
            }
#pragma unroll
            for (int i = 0; i < 2; i++)
#pragma unroll
                for (int j = 0; j < 8; j++) {
                    const uint32_t* bhp = &bh[j >> 1][(j & 1) * 2];
                    const uint32_t* blp = &bl[j >> 1][(j & 1) * 2];
                    mma_bf16(cfr[i][j], ah[i], bhp);
                    mma_bf16(cfr[i][j], ah[i], blp);
                    mma_bf16(cfr[i][j], al[i], bhp);
                }
        }
        __syncthreads();
        p ^= 1;
    }

    const int rbase = m0 + wm + (lane >> 2);
    const int cbase = n0 + wn + (lane & 3) * 2;
#pragma unroll
    for (int i = 0; i < 2; i++) {
#pragma unroll
        for (int j = 0; j < 8; j++) {
            int col  = cbase + j * 8;
            float2 bv = *reinterpret_cast<const float2*>(&bias[col]);
            int row0 = rbase + i * 16;
            int row1 = row0 + 8;
            if (row0 < Mr) {
                float2 v = make_float2(cfr[i][j][0] + bv.x, cfr[i][j][1] + bv.y);
                *reinterpret_cast<float2*>(&C[(size_t)row0 * N + col]) = v;
            }
            if (row1 < Mr) {
                float2 v = make_float2(cfr[i][j][2] + bv.x, cfr[i][j][3] + bv.y);
                *reinterpret_cast<float2*>(&C[(size_t)row1 * N + col]) = v;
            }
        }
    }
#undef ISSUE_STAGE
}

// ---------------- persistent bidirectional GRU (R13 + 2-level barrier) ------
__global__ void __launch_bounds__(256, 1) gru_kernel(
        const float* __restrict__ Wh_f, const float* __restrict__ brec_f,
        const float* __restrict__ Wh_b, const float* __restrict__ brec_b) {
    extern __shared__ float sm[];
    float* h_s = sm;              // [B][H] 64KB
    float* W_s = sm + B * H;      // [3*JS][H] 48KB

    const int dir = blockIdx.x >> 6;
    const int jb  = blockIdx.x & (NB - 1);
    const int j0  = jb * JS;
    const int tid = threadIdx.x;
    const int kq  = tid & 7;
    const int bq  = (tid >> 3) & 7;
    const int jj  = tid >> 6;
    const int bown = bq * 4 + kq;      // batch this lane finalizes (kq<4)
    const int grp  = jb >> 3;          // group id 0..7
    const bool leader = (jb & 7) == 0;

    const float* Wh   = dir ? Wh_b   : Wh_f;
    const float* brec = dir ? brec_b : brec_f;
    const float* gx   = g_gx + dir * H3;   // row stride H6

    for (int idx = tid; idx < 3 * JS * H; idx += 256) {
        int k = idx / (3 * JS);
        int r = idx - k * (3 * JS);
        int g = r >> 3;
        int c = r & 7;
        W_s[(g * JS + c) * H + k] = Wh[(size_t)k * H3 + g * H + j0 + c];
    }
    float2 brg[3];
#pragma unroll
    for (int g = 0; g < 3; g++)
        brg[g] = *reinterpret_cast<const float2*>(brec + g * H + j0 + jj * 2);
    __syncthreads();

    float* hbuf0 = g_hbuf[dir][0];
    float* hbuf1 = g_hbuf[dir][1];
    volatile unsigned* gcnt = &g_grp[dir][grp][0];
    volatile unsigned* rcnt = &g_root[dir][0];

    int soff[4];
#pragma unroll
    for (int pp = 0; pp < 4; pp++) {
        int idx = tid * 4 + pp * 1024;
        soff[pp] = (idx >> 7) * H + (idx & 127);
    }
    uint32_t hs_base = (uint32_t)__cvta_generic_to_shared(h_s);

    for (int s = 0; s < T; s++) {
        const int t = dir ? (T - 1 - s) : s;
        const float* hin  = (s & 1) ? hbuf1 : hbuf0;
        float*       hout = (s & 1) ? hbuf0 : hbuf1;

        // stage h in 4 cp.async groups (16KB each)
#pragma unroll
        for (int c = 0; c < 4; c++) {
#pragma unroll
            for (int pp = 0; pp < 4; pp++)
                cp16(hs_base + (soff[pp] + c * 128) * 4, hin + soff[pp] + c * 128);
            cp_commit();
        }

        // gx prefetch: lane kq<4 loads only its own batch
        float2 gxv[3];
        if (kq < 4) {
            size_t gb = ((size_t)bown * T + t) * H6 + j0 + jj * 2;
            gxv[0] = *reinterpret_cast<const float2*>(gx + gb);
            gxv[1] = *reinterpret_cast<const float2*>(gx + gb + H);
            gxv[2] = *reinterpret_cast<const float2*>(gx + gb + 2 * H);
        }

        ull acc[3][2][4];
#pragma unroll
        for (int g = 0; g < 3; g++)
#pragma unroll
            for (int a = 0; a < 2; a++)
#pragma unroll
                for (int c = 0; c < 4; c++) acc[g][a][c] = 0ull;

        const int kbase = kq * 4;
#pragma unroll
        for (int qc = 0; qc < 4; qc++) {
            if (qc == 0) cp_wait<3>();
            else if (qc == 1) cp_wait<2>();
            else if (qc == 2) cp_wait<1>();
            else cp_wait<0>();
            __syncthreads();
#pragma unroll
            for (int i = qc * 4; i < qc * 4 + 4; i++) {
                const int k = kbase + i * 32;
                ulonglong2 w[3][2];
#pragma unroll
                for (int g = 0; g < 3; g++)
#pragma unroll
                    for (int jj2 = 0; jj2 < 2; jj2++)
                        w[g][jj2] = *reinterpret_cast<const ulonglong2*>(
                            &W_s[(g * JS + jj * 2 + jj2) * H + k]);
                ulonglong2 hv[4];
#pragma unroll
                for (int bi = 0; bi < 4; bi++)
                    hv[bi] = *reinterpret_cast<const ulonglong2*>(&h_s[(bq * 4 + bi) * H + k]);
#pragma unroll
                for (int g = 0; g < 3; g++)
#pragma unroll
                    for (int jj2 = 0; jj2 < 2; jj2++)
#pragma unroll
                        for (int bi = 0; bi < 4; bi++) {
                            acc[g][jj2][bi] = fma2(hv[bi].x, w[g][jj2].x, acc[g][jj2][bi]);
                            acc[g][jj2][bi] = fma2(hv[bi].y, w[g][jj2].y, acc[g][jj2][bi]);
                        }
            }
        }

        // pair-sum + reduce over kq lanes (bits 0..2)
        float red[3][2][4];
#pragma unroll
        for (int g = 0; g < 3; g++)
#pragma unroll
            for (int jj2 = 0; jj2 < 2; jj2++)
#pragma unroll
                for (int bi = 0; bi < 4; bi++) {
                    float x = lo2(acc[g][jj2][bi]) + hi2(acc[g][jj2][bi]);
                    x += __shfl_xor_sync(0xffffffffu, x, 1);
                    x += __shfl_xor_sync(0xffffffffu, x, 2);
                    x += __shfl_xor_sync(0xffffffffu, x, 4);
                    red[g][jj2][bi] = x;
                }

        // finalize: lane kq=c handles batch bown (c<4)
        unsigned hi_pack = 0, lo_pack = 0;
        if (kq < 4) {
            const float2 hp = *reinterpret_cast<const float2*>(&h_s[bown * H + j0 + jj * 2]);
            float hn[2];
#pragma unroll
            for (int jj2 = 0; jj2 < 2; jj2++) {
                const float az = red[0][jj2][kq] + ((jj2) ? brg[0].y : brg[0].x);
                const float ar = red[1][jj2][kq] + ((jj2) ? brg[1].y : brg[1].x);
                const float an = red[2][jj2][kq] + ((jj2) ? brg[2].y : brg[2].x);
                const float xz = (jj2) ? gxv[0].y : gxv[0].x;
                const float xr = (jj2) ? gxv[1].y : gxv[1].x;
                const float xn = (jj2) ? gxv[2].y : gxv[2].x;
                const float hprev = (jj2) ? hp.y : hp.x;
                const float zg = 1.f / (1.f + expf(-(xz + az)));
                const float rg = 1.f / (1.f + expf(-(xr + ar)));
                const float hc = tanhf(xn + rg * an);
                hn[jj2] = zg * hprev + (1.f - zg) * hc;
            }
            asm volatile("st.global.cg.v2.f32 [%0], {%1, %2};"
                         :: "l"(hout + bown * H + j0 + jj * 2), "f"(hn[0]), "f"(hn[1]));
            __nv_bfloat16 h0 = __float2bfloat16(hn[0]);
            __nv_bfloat16 h1 = __float2bfloat16(hn[1]);
            __nv_bfloat16 l0 = __float2bfloat16(hn[0] - __bfloat162float(h0));
            __nv_bfloat16 l1 = __float2bfloat16(hn[1] - __bfloat162float(h1));
            hi_pack = (unsigned)*reinterpret_cast<unsigned short*>(&h0)
                    | ((unsigned)*reinterpret_cast<unsigned short*>(&h1) << 16);
            lo_pack = (unsigned)*reinterpret_cast<unsigned short*>(&l0)
                    | ((unsigned)*reinterpret_cast<unsigned short*>(&l1) << 16);
        }

        // arrive early on GROUP counter (8 atomics per line, parallel lines)
        __syncthreads();
        if (tid == 0) {
            __threadfence();
            atomicAdd((unsigned*)gcnt, 1u);
        }

        // outcat split-bf16 store (+ final h rows BT..)
        if (kq < 4) {
            size_t o = ((size_t)bown * T + t) * H2 + dir * H + j0 + jj * 2;
            *reinterpret_cast<unsigned*>(&g_oc_hi[o]) = hi_pack;
            *reinterpret_cast<unsigned*>(&g_oc_lo[o]) = lo_pack;
            if (s == T - 1) {
                size_t o2 = ((size_t)(BT + bown)) * H2 + dir * H + j0 + jj * 2;
                *reinterpret_cast<unsigned*>(&g_oc_hi[o2]) = hi_pack;
                *reinterpret_cast<unsigned*>(&g_oc_lo[o2]) = lo_pack;
            }
        }

        // two-level wait: leader promotes group completion to root; all spin root.
        // A block can only arrive for step s+1 after root-release(s), so a group
        // counter at observation time contains ONLY step<=s arrivals (no overshoot).
        if (tid == 0) {
            const unsigned tgt = 8u * (unsigned)(s + 1);
            if (leader) {
                while (*gcnt < tgt) {}
                __threadfence();               // order group observation before root publish
                atomicAdd((unsigned*)rcnt, 1u);
            }
            while (*rcnt < tgt) {}
            __threadfence();
        }
        __syncthreads();
    }
}

// ---------------- launch ----------------
extern "C" void kernel_launch(void* const* d_in, const int* in_sizes, int n_in,
                              void* d_out, int out_size) {
    (void)in_sizes; (void)n_in; (void)out_size;
    const int*   seqs = (const int*)d_in[0];
    const float* emb  = (const float*)d_in[2];
    const float* Wx_f = (const float*)d_in[3];
    const float* Wh_f = (const float*)d_in[4];
    const float* b_f  = (const float*)d_in[5];
    const float* Wx_b = (const float*)d_in[6];
    const float* Wh_b = (const float*)d_in[7];
    const float* b_b  = (const float*)d_in[8];
    const float* Wd   = (const float*)d_in[9];
    const float* bd   = (const float*)d_in[10];
    float* out = (float*)d_out;

    const int smem_gru = (B * H + 3 * JS * H) * (int)sizeof(float); // 112 KB
    cudaFuncSetAttribute(gru_kernel, cudaFuncAttributeMaxDynamicSharedMemorySize, smem_gru);
    cudaFuncSetAttribute(gemm_bf16_kernel, cudaFuncAttributeMaxDynamicSharedMemorySize, GEMM_SMEM_BYTES);

    __nv_bfloat16 *p_exh, *p_exl, *p_wch, *p_wcl, *p_wdh, *p_wdl, *p_och, *p_ocl;
    float *p_gx, *p_bcat;
    cudaGetSymbolAddress((void**)&p_exh, g_embx_hi);
    cudaGetSymbolAddress((void**)&p_exl, g_embx_lo);
    cudaGetSymbolAddress((void**)&p_wch, g_wxc_hi);
    cudaGetSymbolAddress((void**)&p_wcl, g_wxc_lo);
    cudaGetSymbolAddress((void**)&p_wdh, g_wd_hi);
    cudaGetSymbolAddress((void**)&p_wdl, g_wd_lo);
    cudaGetSymbolAddress((void**)&p_och, g_oc_hi);
    cudaGetSymbolAddress((void**)&p_ocl, g_oc_lo);
    cudaGetSymbolAddress((void**)&p_gx,  g_gx);
    cudaGetSymbolAddress((void**)&p_bcat, g_bcat);

    init_kernel<<<64, 256>>>();
    embed_kernel<<<BT, 128>>>(seqs, emb);

    split_cat_kernel<<<(H * H3 + 255) / 256, 256>>>(Wx_f, p_wch, p_wcl, H, H3, H6, 0);
    split_cat_kernel<<<(H * H3 + 255) / 256, 256>>>(Wx_b, p_wch, p_wcl, H, H3, H6, H3);
    split_kernel<<<(H2 * H + 255) / 256, 256>>>(Wd, p_wdh, p_wdl, H2 * H);
    bias_cat_kernel<<<(H3 + 255) / 256, 256>>>(b_f, b_b);

    // single merged gx GEMM: [BT,512] @ [512,3072] + bcat
    gemm_bf16_kernel<<<dim3(H6 / 128, BT / 128), 256, GEMM_SMEM_BYTES>>>(
        p_exh, p_exl, p_wch, p_wcl, p_bcat, p_gx, BT, H6, H);

    gru_kernel<<<2 * NB, 256, smem_gru>>>(Wh_f, b_f + H3, Wh_b, b_b + H3);

    // merged projection: rows 0..BT-1 outputs, BT..BT+B-1 hidden
    gemm_bf16_kernel<<<dim3(H / 128, (BT + B + 127) / 128), 256, GEMM_SMEM_BYTES>>>(
        p_och, p_ocl, p_wdh, p_wdl, bd, out, BT + B, H, H2);
}

// round 15
// speedup vs baseline: 1.1226x; 1.1226x over previous
#include <cuda_runtime.h>
#include <cuda_bf16.h>
#include <cstdint>

#define B   32
#define T   512
#define MIN 4
#define H   512
#define H2  1024
#define H3  1536
#define H6  3072
#define BT  (B*T)

#define NB  64
#define JS  8

typedef unsigned long long ull;

// ---------------- packed f32x2 helpers ----------------
__device__ __forceinline__ ull fma2(ull a, ull b, ull c) {
    ull d;
    asm("fma.rn.f32x2 %0, %1, %2, %3;" : "=l"(d) : "l"(a), "l"(b), "l"(c));
    return d;
}
__device__ __forceinline__ float lo2(ull v) { return __uint_as_float((unsigned)v); }
__device__ __forceinline__ float hi2(ull v) { return __uint_as_float((unsigned)(v >> 32)); }

// ---------------- cp.async helpers ----------------
__device__ __forceinline__ void cp16(uint32_t smem, const void* gmem) {
    asm volatile("cp.async.cg.shared.global [%0], [%1], 16;" :: "r"(smem), "l"(gmem));
}
__device__ __forceinline__ void cp_commit() {
    asm volatile("cp.async.commit_group;");
}
template <int N>
__device__ __forceinline__ void cp_wait() {
    asm volatile("cp.async.wait_group %0;" :: "n"(N));
}

// ---------------- tensor-core helpers ----------------
__device__ __forceinline__ void ldm_x4(uint32_t* r, uint32_t addr) {
    asm volatile("ldmatrix.sync.aligned.m8n8.x4.shared.b16 {%0,%1,%2,%3}, [%4];"
        : "=r"(r[0]), "=r"(r[1]), "=r"(r[2]), "=r"(r[3]) : "r"(addr));
}
__device__ __forceinline__ void ldm_x4_t(uint32_t* r, uint32_t addr) {
    asm volatile("ldmatrix.sync.aligned.m8n8.x4.trans.shared.b16 {%0,%1,%2,%3}, [%4];"
        : "=r"(r[0]), "=r"(r[1]), "=r"(r[2]), "=r"(r[3]) : "r"(addr));
}
__device__ __forceinline__ void mma_bf16(float* c, const uint32_t* a, const uint32_t* b) {
    asm volatile("mma.sync.aligned.m16n8k16.row.col.f32.bf16.bf16.f32 "
        "{%0,%1,%2,%3}, {%4,%5,%6,%7}, {%8,%9}, {%0,%1,%2,%3};"
        : "+f"(c[0]), "+f"(c[1]), "+f"(c[2]), "+f"(c[3])
        : "r"(a[0]), "r"(a[1]), "r"(a[2]), "r"(a[3]), "r"(b[0]), "r"(b[1]));
}

// ---------------- device scratch ----------------
__device__ __align__(16) __nv_bfloat16 g_embx_hi[BT * H];
__device__ __align__(16) __nv_bfloat16 g_embx_lo[BT * H];
__device__ __align__(16) __nv_bfloat16 g_wxc_hi[(size_t)H * H6];   // [Wx_f | Wx_b]
__device__ __align__(16) __nv_bfloat16 g_wxc_lo[(size_t)H * H6];
__device__ __align__(16) __nv_bfloat16 g_wd_hi[H2 * H];
__device__ __align__(16) __nv_bfloat16 g_wd_lo[H2 * H];
__device__ __align__(16) __nv_bfloat16 g_oc_hi[(size_t)(BT + B) * H2];
__device__ __align__(16) __nv_bfloat16 g_oc_lo[(size_t)(BT + B) * H2];
__device__ float    g_bcat[H6];                 // [b_f_in | b_b_in]
__device__ float    g_gx[(size_t)BT * H6];      // [bt][f 0..1535 | b 1536..3071]
__device__ float    g_hbuf[2][2][B * H];
__device__ unsigned g_bar[2];                   // FROZEN single-counter barrier

// ---------------- init ----------------
__global__ void init_kernel() {
    int tid = blockIdx.x * blockDim.x + threadIdx.x;
    if (tid < 2) g_bar[tid] = 0;
    for (int i = tid; i < B * H; i += gridDim.x * blockDim.x) {
        g_hbuf[0][0][i] = 0.f;
        g_hbuf[1][0][i] = 0.f;
    }
}

// ---------------- split fp32 -> (hi, lo) bf16, plain ----------------
__global__ void split_kernel(const float* __restrict__ src,
                             __nv_bfloat16* __restrict__ hi,
                             __nv_bfloat16* __restrict__ lo, int n) {
    int i = blockIdx.x * blockDim.x + threadIdx.x;
    if (i < n) {
        float x = src[i];
        __nv_bfloat16 h = __float2bfloat16(x);
        hi[i] = h;
        lo[i] = __float2bfloat16(x - __bfloat162float(h));
    }
}

// ---------------- split into concatenated layout ----------------
__global__ void split_cat_kernel(const float* __restrict__ src,
                                 __nv_bfloat16* __restrict__ hi,
                                 __nv_bfloat16* __restrict__ lo,
                                 int rows, int cols, int ldo, int coloff) {
    int i = blockIdx.x * blockDim.x + threadIdx.x;
    if (i < rows * cols) {
        int r = i / cols;
        int c = i - r * cols;
        float x = src[i];
        __nv_bfloat16 h = __float2bfloat16(x);
        size_t o = (size_t)r * ldo + coloff + c;
        hi[o] = h;
        lo[o] = __float2bfloat16(x - __bfloat162float(h));
    }
}

// ---------------- bias concat ----------------
__global__ void bias_cat_kernel(const float* __restrict__ bf_,
                                const float* __restrict__ bb_) {
    int i = blockIdx.x * blockDim.x + threadIdx.x;
    if (i < H3) {
        g_bcat[i]      = bf_[i];
        g_bcat[H3 + i] = bb_[i];
    }
}

// ---------------- embedding gather + sum -> split bf16 ----------------
__global__ void embed_kernel(const int* __restrict__ seqs,
                             const float* __restrict__ emb) {
    int bt = blockIdx.x;
    int i4 = threadIdx.x * 4;
    const int* s = seqs + bt * MIN;
    float acc[4] = {0.f, 0.f, 0.f, 0.f};
#pragma unroll
    for (int m = 0; m < MIN; m++) {
        size_t row = (size_t)s[m] * H;
        float4 v = *reinterpret_cast<const float4*>(emb + row + i4);
        acc[0] += v.x; acc[1] += v.y; acc[2] += v.z; acc[3] += v.w;
    }
    __nv_bfloat16 hv[4], lv[4];
#pragma unroll
    for (int q = 0; q < 4; q++) {
        hv[q] = __float2bfloat16(acc[q]);
        lv[q] = __float2bfloat16(acc[q] - __bfloat162float(hv[q]));
    }
    size_t o = (size_t)bt * H + i4;
    *reinterpret_cast<ull*>(&g_embx_hi[o]) = *reinterpret_cast<ull*>(hv);
    *reinterpret_cast<ull*>(&g_embx_lo[o]) = *reinterpret_cast<ull*>(lv);
}

// ---------------- split-bf16 tensor-core GEMM (R13, unchanged) ----------------
#define AS_STRIDE 40
#define BS_STRIDE 136
#define AS_BUF (128 * AS_STRIDE)
#define BS_BUF (32 * BS_STRIDE)
#define OFF_AHI 0
#define OFF_ALO (2 * AS_BUF)
#define OFF_BHI (4 * AS_BUF)
#define OFF_BLO (4 * AS_BUF + 2 * BS_BUF)
#define GEMM_SMEM_BYTES (2 * (4 * AS_BUF + 4 * BS_BUF))

__global__ void __launch_bounds__(256, 1) gemm_bf16_kernel(
        const __nv_bfloat16* __restrict__ Ahi, const __nv_bfloat16* __restrict__ Alo,
        const __nv_bfloat16* __restrict__ Bhi, const __nv_bfloat16* __restrict__ Blo,
        const float* __restrict__ bias, float* __restrict__ C,
        int Mr, int N, int K) {
    extern __shared__ __nv_bfloat16 smem_bf[];
    const uint32_t sbase = (uint32_t)__cvta_generic_to_shared(smem_bf);
    const int tid  = threadIdx.x;
    const int lane = tid & 31;
    const int wid  = tid >> 5;
    const int m0 = blockIdx.y * 128;
    const int n0 = blockIdx.x * 128;
    const int wm = (wid & 3) * 32;
    const int wn = (wid >> 2) * 64;

    int aRow[2], aCol[2], bRow[2], bCol[2];
    bool aOk[2];
#pragma unroll
    for (int l = 0; l < 2; l++) {
        int c = tid + l * 256;
        aRow[l] = c >> 2;  aCol[l] = (c & 3) * 8;
        bRow[l] = c >> 4;  bCol[l] = (c & 15) * 8;
        aOk[l] = (m0 + aRow[l]) < Mr;
    }

#define ISSUE_STAGE(KT, P) do {                                                   \
    _Pragma("unroll")                                                             \
    for (int l = 0; l < 2; l++) {                                                 \
        if (aOk[l]) {                                                             \
            size_t go = (size_t)(m0 + aRow[l]) * K + (KT) + aCol[l];              \
            uint32_t so = (uint32_t)((P) * AS_BUF + aRow[l] * AS_STRIDE + aCol[l]); \
            cp16(sbase + 2u * (OFF_AHI + so), Ahi + go);                          \
            cp16(sbase + 2u * (OFF_ALO + so), Alo + go);                          \
        }                                                                         \
        {                                                                         \
            size_t go = (size_t)((KT) + bRow[l]) * N + n0 + bCol[l];              \
            uint32_t so = (uint32_t)((P) * BS_BUF + bRow[l] * BS_STRIDE + bCol[l]); \
            cp16(sbase + 2u * (OFF_BHI + so), Bhi + go);                          \
            cp16(sbase + 2u * (OFF_BLO + so), Blo + go);                          \
        }                                                                         \
    }                                                                             \
    cp_commit();                                                                  \
} while (0)

    float cfr[2][8][4];
#pragma unroll
    for (int i = 0; i < 2; i++)
#pragma unroll
        for (int j = 0; j < 8; j++)
#pragma unroll
            for (int q = 0; q < 4; q++) cfr[i][j][q] = 0.f;

    ISSUE_STAGE(0, 0);
    int p = 0;
    for (int kt = 0; kt < K; kt += 32) {
        const bool more = (kt + 32) < K;
        if (more) { ISSUE_STAGE(kt + 32, p ^ 1); cp_wait<1>(); }
        else      { cp_wait<0>(); }
        __syncthreads();

#pragma unroll
        for (int kk = 0; kk < 2; kk++) {
            uint32_t ah[2][4], al[2][4];
#pragma unroll
            for (int i = 0; i < 2; i++) {
                int r  = wm + i * 16 + (lane & 15);
                int cc = kk * 16 + ((lane >> 4) << 3);
                uint32_t ao = (uint32_t)(p * AS_BUF + r * AS_STRIDE + cc);
                ldm_x4(ah[i], sbase + 2u * (OFF_AHI + ao));
                ldm_x4(al[i], sbase + 2u * (OFF_ALO + ao));
            }
            uint32_t bh[4][4], bl[4][4];
#pragma unroll
            for (int j2 = 0; j2 < 4; j2++) {
                int kr = kk * 16 + (lane & 15);
                int nc = wn + j2 * 16 + ((lane >> 4) << 3);
                uint32_t bo = (uint32_t)(p * BS_BUF + kr * BS_STRIDE + nc);
                ldm_x4_t(bh[j2], sbase + 2u * (OFF_BHI + bo));
                ldm_x4_t(bl[j2], sbase + 2u * (OFF_BLO + bo));
            }
#pragma unroll
            for (int i = 0; i < 2; i++)
#pragma unroll
                for (int j = 0; j < 8; j++) {
                    const uint32_t* bhp = &bh[j >> 1][(j & 1) * 2];
                    const uint32_t* blp = &bl[j >> 1][(j & 1) * 2];
                    mma_bf16(cfr[i][j], ah[i], bhp);
                    mma_bf16(cfr[i][j], ah[i], blp);
                    mma_bf16(cfr[i][j], al[i], bhp);
                }
        }
        __syncthreads();
        p ^= 1;
    }

    const int rbase = m0 + wm + (lane >> 2);
    const int cbase = n0 + wn + (lane & 3) * 2;
#pragma unroll
    for (int i = 0; i < 2; i++) {
#pragma unroll
        for (int j = 0; j < 8; j++) {
            int col  = cbase + j * 8;
            float2 bv = *reinterpret_cast<const float2*>(&bias[col]);
            int row0 = rbase + i * 16;
            int row1 = row0 + 8;
            if (row0 < Mr) {
                float2 v = make_float2(cfr[i][j][0] + bv.x, cfr[i][j][1] + bv.y);
                *reinterpret_cast<float2*>(&C[(size_t)row0 * N + col]) = v;
            }
            if (row1 < Mr) {
                float2 v = make_float2(cfr[i][j][2] + bv.x, cfr[i][j][3] + bv.y);
                *reinterpret_cast<float2*>(&C[(size_t)row1 * N + col]) = v;
            }
        }
    }
#undef ISSUE_STAGE
}

// ---------------- persistent bidirectional GRU (R13, single-counter barrier) -
__global__ void __launch_bounds__(256, 1) gru_kernel(
        const float* __restrict__ Wh_f, const float* __restrict__ brec_f,
        const float* __restrict__ Wh_b, const float* __restrict__ brec_b) {
    extern __shared__ float sm[];
    float* h_s = sm;              // [B][H] 64KB
    float* W_s = sm + B * H;      // [3*JS][H] 48KB

    const int dir = blockIdx.x >> 6;
    const int jb  = blockIdx.x & (NB - 1);
    const int j0  = jb * JS;
    const int tid = threadIdx.x;
    const int kq  = tid & 7;
    const int bq  = (tid >> 3) & 7;
    const int jj  = tid >> 6;
    const int bown = bq * 4 + kq;      // batch this lane finalizes (kq<4)

    const float* Wh   = dir ? Wh_b   : Wh_f;
    const float* brec = dir ? brec_b : brec_f;
    const float* gx   = g_gx + dir * H3;   // row stride H6

    for (int idx = tid; idx < 3 * JS * H; idx += 256) {
        int k = idx / (3 * JS);
        int r = idx - k * (3 * JS);
        int g = r >> 3;
        int c = r & 7;
        W_s[(g * JS + c) * H + k] = Wh[(size_t)k * H3 + g * H + j0 + c];
    }
    float2 brg[3];
#pragma unroll
    for (int g = 0; g < 3; g++)
        brg[g] = *reinterpret_cast<const float2*>(brec + g * H + j0 + jj * 2);
    __syncthreads();

    float* hbuf0 = g_hbuf[dir][0];
    float* hbuf1 = g_hbuf[dir][1];
    volatile unsigned* bar = &g_bar[dir];

    int soff[4];
#pragma unroll
    for (int pp = 0; pp < 4; pp++) {
        int idx = tid * 4 + pp * 1024;
        soff[pp] = (idx >> 7) * H + (idx & 127);
    }
    uint32_t hs_base = (uint32_t)__cvta_generic_to_shared(h_s);

    for (int s = 0; s < T; s++) {
        const int t = dir ? (T - 1 - s) : s;
        const float* hin  = (s & 1) ? hbuf1 : hbuf0;
        float*       hout = (s & 1) ? hbuf0 : hbuf1;

        // stage h in 4 cp.async groups (16KB each)
#pragma unroll
        for (int c = 0; c < 4; c++) {
#pragma unroll
            for (int pp = 0; pp < 4; pp++)
                cp16(hs_base + (soff[pp] + c * 128) * 4, hin + soff[pp] + c * 128);
            cp_commit();
        }

        // gx prefetch: lane kq<4 loads only its own batch
        float2 gxv[3];
        if (kq < 4) {
            size_t gb = ((size_t)bown * T + t) * H6 + j0 + jj * 2;
            gxv[0] = *reinterpret_cast<const float2*>(gx + gb);
            gxv[1] = *reinterpret_cast<const float2*>(gx + gb + H);
            gxv[2] = *reinterpret_cast<const float2*>(gx + gb + 2 * H);
        }

        ull acc[3][2][4];
#pragma unroll
        for (int g = 0; g < 3; g++)
#pragma unroll
            for (int a = 0; a < 2; a++)
#pragma unroll
                for (int c = 0; c < 4; c++) acc[g][a][c] = 0ull;

        const int kbase = kq * 4;
#pragma unroll
        for (int qc = 0; qc < 4; qc++) {
            if (qc == 0) cp_wait<3>();
            else if (qc == 1) cp_wait<2>();
            else if (qc == 2) cp_wait<1>();
            else cp_wait<0>();
            __syncthreads();
#pragma unroll
            for (int i = qc * 4; i < qc * 4 + 4; i++) {
                const int k = kbase + i * 32;
                ulonglong2 w[3][2];
#pragma unroll
                for (int g = 0; g < 3; g++)
#pragma unroll
                    for (int jj2 = 0; jj2 < 2; jj2++)
                        w[g][jj2] = *reinterpret_cast<const ulonglong2*>(
                            &W_s[(g * JS + jj * 2 + jj2) * H + k]);
                ulonglong2 hv[4];
#pragma unroll
                for (int bi = 0; bi < 4; bi++)
                    hv[bi] = *reinterpret_cast<const ulonglong2*>(&h_s[(bq * 4 + bi) * H + k]);
#pragma unroll
                for (int g = 0; g < 3; g++)
#pragma unroll
                    for (int jj2 = 0; jj2 < 2; jj2++)
#pragma unroll
                        for (int bi = 0; bi < 4; bi++) {
                            acc[g][jj2][bi] = fma2(hv[bi].x, w[g][jj2].x, acc[g][jj2][bi]);
                            acc[g][jj2][bi] = fma2(hv[bi].y, w[g][jj2].y, acc[g][jj2][bi]);
                        }
            }
        }

        // pair-sum + reduce over kq lanes (bits 0..2)
        float red[3][2][4];
#pragma unroll
        for (int g = 0; g < 3; g++)
#pragma unroll
            for (int jj2 = 0; jj2 < 2; jj2++)
#pragma unroll
                for (int bi = 0; bi < 4; bi++) {
                    float x = lo2(acc[g][jj2][bi]) + hi2(acc[g][jj2][bi]);
                    x += __shfl_xor_sync(0xffffffffu, x, 1);
                    x += __shfl_xor_sync(0xffffffffu, x, 2);
                    x += __shfl_xor_sync(0xffffffffu, x, 4);
                    red[g][jj2][bi] = x;
                }

        // finalize: lane kq=c handles batch bown (c<4)
        unsigned hi_pack = 0, lo_pack = 0;
        if (kq < 4) {
            const float2 hp = *reinterpret_cast<const float2*>(&h_s[bown * H + j0 + jj * 2]);
            float hn[2];
#pragma unroll
            for (int jj2 = 0; jj2 < 2; jj2++) {
                const float az = red[0][jj2][kq] + ((jj2) ? brg[0].y : brg[0].x);
                const float ar = red[1][jj2][kq] + ((jj2) ? brg[1].y : brg[1].x);
                const float an = red[2][jj2][kq] + ((jj2) ? brg[2].y : brg[2].x);
                const float xz = (jj2) ? gxv[0].y : gxv[0].x;
                const float xr = (jj2) ? gxv[1].y : gxv[1].x;
                const float xn = (jj2) ? gxv[2].y : gxv[2].x;
                const float hprev = (jj2) ? hp.y : hp.x;
                const float zg = 1.f / (1.f + expf(-(xz + az)));
                const float rg = 1.f / (1.f + expf(-(xr + ar)));
                const float hc = tanhf(xn + rg * an);
                hn[jj2] = zg * hprev + (1.f - zg) * hc;
            }
            asm volatile("st.global.cg.v2.f32 [%0], {%1, %2};"
                         :: "l"(hout + bown * H + j0 + jj * 2), "f"(hn[0]), "f"(hn[1]));
            __nv_bfloat16 h0 = __float2bfloat16(hn[0]);
            __nv_bfloat16 h1 = __float2bfloat16(hn[1]);
            __nv_bfloat16 l0 = __float2bfloat16(hn[0] - __bfloat162float(h0));
            __nv_bfloat16 l1 = __float2bfloat16(hn[1] - __bfloat162float(h1));
            hi_pack = (unsigned)*reinterpret_cast<unsigned short*>(&h0)
                    | ((unsigned)*reinterpret_cast<unsigned short*>(&h1) << 16);
            lo_pack = (unsigned)*reinterpret_cast<unsigned short*>(&l0)
                    | ((unsigned)*reinterpret_cast<unsigned short*>(&l1) << 16);
        }

        // arrive early: h published; outcat happens while others arrive
        __syncthreads();
        if (tid == 0) {
            __threadfence();
            atomicAdd((unsigned*)bar, 1u);
        }

        // outcat split-bf16 store (+ final h rows BT..)
        if (kq < 4) {
            size_t o = ((size_t)bown * T + t) * H2 + dir * H + j0 + jj * 2;
            *reinterpret_cast<unsigned*>(&g_oc_hi[o]) = hi_pack;
            *reinterpret_cast<unsigned*>(&g_oc_lo[o]) = lo_pack;
            if (s == T - 1) {
                size_t o2 = ((size_t)(BT + bown)) * H2 + dir * H + j0 + jj * 2;
                *reinterpret_cast<unsigned*>(&g_oc_hi[o2]) = hi_pack;
                *reinterpret_cast<unsigned*>(&g_oc_lo[o2]) = lo_pack;
            }
        }

        // wait: tid0-only direct spin on the single counter (FROZEN pattern)
        if (tid == 0) {
            const unsigned target = (unsigned)(NB * (s + 1));
            while (*bar < target) {}
            __threadfence();
        }
        __syncthreads();
    }
}

// ---------------- launch ----------------
extern "C" void kernel_launch(void* const* d_in, const int* in_sizes, int n_in,
                              void* d_out, int out_size) {
    (void)in_sizes; (void)n_in; (void)out_size;
    const int*   seqs = (const int*)d_in[0];
    const float* emb  = (const float*)d_in[2];
    const float* Wx_f = (const float*)d_in[3];
    const float* Wh_f = (const float*)d_in[4];
    const float* b_f  = (const float*)d_in[5];
    const float* Wx_b = (const float*)d_in[6];
    const float* Wh_b = (const float*)d_in[7];
    const float* b_b  = (const float*)d_in[8];
    const float* Wd   = (const float*)d_in[9];
    const float* bd   = (const float*)d_in[10];
    float* out = (float*)d_out;

    const int smem_gru = (B * H + 3 * JS * H) * (int)sizeof(float); // 112 KB
    cudaFuncSetAttribute(gru_kernel, cudaFuncAttributeMaxDynamicSharedMemorySize, smem_gru);
    cudaFuncSetAttribute(gemm_bf16_kernel, cudaFuncAttributeMaxDynamicSharedMemorySize, GEMM_SMEM_BYTES);

    __nv_bfloat16 *p_exh, *p_exl, *p_wch, *p_wcl, *p_wdh, *p_wdl, *p_och, *p_ocl;
    float *p_gx, *p_bcat;
    cudaGetSymbolAddress((void**)&p_exh, g_embx_hi);
    cudaGetSymbolAddress((void**)&p_exl, g_embx_lo);
    cudaGetSymbolAddress((void**)&p_wch, g_wxc_hi);
    cudaGetSymbolAddress((void**)&p_wcl, g_wxc_lo);
    cudaGetSymbolAddress((void**)&p_wdh, g_wd_hi);
    cudaGetSymbolAddress((void**)&p_wdl, g_wd_lo);
    cudaGetSymbolAddress((void**)&p_och, g_oc_hi);
    cudaGetSymbolAddress((void**)&p_ocl, g_oc_lo);
    cudaGetSymbolAddress((void**)&p_gx,  g_gx);
    cudaGetSymbolAddress((void**)&p_bcat, g_bcat);

    init_kernel<<<64, 256>>>();
    embed_kernel<<<BT, 128>>>(seqs, emb);

    split_cat_kernel<<<(H * H3 + 255) / 256, 256>>>(Wx_f, p_wch, p_wcl, H, H3, H6, 0);
    split_cat_kernel<<<(H * H3 + 255) / 256, 256>>>(Wx_b, p_wch, p_wcl, H, H3, H6, H3);
    split_kernel<<<(H2 * H + 255) / 256, 256>>>(Wd, p_wdh, p_wdl, H2 * H);
    bias_cat_kernel<<<(H3 + 255) / 256, 256>>>(b_f, b_b);

    // single merged gx GEMM: [BT,512] @ [512,3072] + bcat
    gemm_bf16_kernel<<<dim3(H6 / 128, BT / 128), 256, GEMM_SMEM_BYTES>>>(
        p_exh, p_exl, p_wch, p_wcl, p_bcat, p_gx, BT, H6, H);

    gru_kernel<<<2 * NB, 256, smem_gru>>>(Wh_f, b_f + H3, Wh_b, b_b + H3);

    // merged projection: rows 0..BT-1 outputs, BT..BT+B-1 hidden
    gemm_bf16_kernel<<<dim3(H / 128, (BT + B + 127) / 128), 256, GEMM_SMEM_BYTES>>>(
        p_och, p_ocl, p_wdh, p_wdl, bd, out, BT + B, H, H2);
}

// round 16
// speedup vs baseline: 1.1674x; 1.0399x over previous
#include <cuda_runtime.h>
#include <cuda_bf16.h>
#include <cstdint>

#define B   32
#define T   512
#define MIN 4
#define H   512
#define H2  1024
#define H3  1536
#define H6  3072
#define BT  (B*T)

#define NB  64
#define JS  8

typedef unsigned long long ull;

// ---------------- packed f32x2 helpers ----------------
__device__ __forceinline__ ull fma2(ull a, ull b, ull c) {
    ull d;
    asm("fma.rn.f32x2 %0, %1, %2, %3;" : "=l"(d) : "l"(a), "l"(b), "l"(c));
    return d;
}
__device__ __forceinline__ float lo2(ull v) { return __uint_as_float((unsigned)v); }
__device__ __forceinline__ float hi2(ull v) { return __uint_as_float((unsigned)(v >> 32)); }

// ---------------- cp.async helpers ----------------
__device__ __forceinline__ void cp16(uint32_t smem, const void* gmem) {
    asm volatile("cp.async.cg.shared.global [%0], [%1], 16;" :: "r"(smem), "l"(gmem));
}
__device__ __forceinline__ void cp_commit() {
    asm volatile("cp.async.commit_group;");
}
template <int N>
__device__ __forceinline__ void cp_wait() {
    asm volatile("cp.async.wait_group %0;" :: "n"(N));
}

// ---------------- tensor-core helpers ----------------
__device__ __forceinline__ void ldm_x4(uint32_t* r, uint32_t addr) {
    asm volatile("ldmatrix.sync.aligned.m8n8.x4.shared.b16 {%0,%1,%2,%3}, [%4];"
        : "=r"(r[0]), "=r"(r[1]), "=r"(r[2]), "=r"(r[3]) : "r"(addr));
}
__device__ __forceinline__ void ldm_x4_t(uint32_t* r, uint32_t addr) {
    asm volatile("ldmatrix.sync.aligned.m8n8.x4.trans.shared.b16 {%0,%1,%2,%3}, [%4];"
        : "=r"(r[0]), "=r"(r[1]), "=r"(r[2]), "=r"(r[3]) : "r"(addr));
}
__device__ __forceinline__ void mma_bf16(float* c, const uint32_t* a, const uint32_t* b) {
    asm volatile("mma.sync.aligned.m16n8k16.row.col.f32.bf16.bf16.f32 "
        "{%0,%1,%2,%3}, {%4,%5,%6,%7}, {%8,%9}, {%0,%1,%2,%3};"
        : "+f"(c[0]), "+f"(c[1]), "+f"(c[2]), "+f"(c[3])
        : "r"(a[0]), "r"(a[1]), "r"(a[2]), "r"(a[3]), "r"(b[0]), "r"(b[1]));
}

// ---------------- device scratch ----------------
__device__ __align__(16) __nv_bfloat16 g_embx_hi[BT * H];
__device__ __align__(16) __nv_bfloat16 g_embx_lo[BT * H];
__device__ __align__(16) __nv_bfloat16 g_wxc_hi[(size_t)H * H6];   // [Wx_f | Wx_b]
__device__ __align__(16) __nv_bfloat16 g_wxc_lo[(size_t)H * H6];
__device__ __align__(16) __nv_bfloat16 g_wd_hi[H2 * H];
__device__ __align__(16) __nv_bfloat16 g_wd_lo[H2 * H];
__device__ __align__(16) __nv_bfloat16 g_oc_hi[(size_t)(BT + B) * H2];
__device__ __align__(16) __nv_bfloat16 g_oc_lo[(size_t)(BT + B) * H2];
__device__ float    g_bcat[H6];                 // [b_f_in | b_b_in]
__device__ float    g_gx[(size_t)BT * H6];      // [bt][f 0..1535 | b 1536..3071]
__device__ float    g_hbuf[2][2][B * H];
__device__ unsigned g_bar[2];                   // FROZEN single-counter barrier

// ---------------- init ----------------
__global__ void init_kernel() {
    int tid = blockIdx.x * blockDim.x + threadIdx.x;
    if (tid < 2) g_bar[tid] = 0;
    for (int i = tid; i < B * H; i += gridDim.x * blockDim.x) {
        g_hbuf[0][0][i] = 0.f;
        g_hbuf[1][0][i] = 0.f;
    }
}

// ---------------- split fp32 -> (hi, lo) bf16, plain ----------------
__global__ void split_kernel(const float* __restrict__ src,
                             __nv_bfloat16* __restrict__ hi,
                             __nv_bfloat16* __restrict__ lo, int n) {
    int i = blockIdx.x * blockDim.x + threadIdx.x;
    if (i < n) {
        float x = src[i];
        __nv_bfloat16 h = __float2bfloat16(x);
        hi[i] = h;
        lo[i] = __float2bfloat16(x - __bfloat162float(h));
    }
}

// ---------------- split into concatenated layout ----------------
__global__ void split_cat_kernel(const float* __restrict__ src,
                                 __nv_bfloat16* __restrict__ hi,
                                 __nv_bfloat16* __restrict__ lo,
                                 int rows, int cols, int ldo, int coloff) {
    int i = blockIdx.x * blockDim.x + threadIdx.x;
    if (i < rows * cols) {
        int r = i / cols;
        int c = i - r * cols;
        float x = src[i];
        __nv_bfloat16 h = __float2bfloat16(x);
        size_t o = (size_t)r * ldo + coloff + c;
        hi[o] = h;
        lo[o] = __float2bfloat16(x - __bfloat162float(h));
    }
}

// ---------------- bias concat ----------------
__global__ void bias_cat_kernel(const float* __restrict__ bf_,
                                const float* __restrict__ bb_) {
    int i = blockIdx.x * blockDim.x + threadIdx.x;
    if (i < H3) {
        g_bcat[i]      = bf_[i];
        g_bcat[H3 + i] = bb_[i];
    }
}

// ---------------- embedding gather + sum -> split bf16 ----------------
__global__ void embed_kernel(const int* __restrict__ seqs,
                             const float* __restrict__ emb) {
    int bt = blockIdx.x;
    int i4 = threadIdx.x * 4;
    const int* s = seqs + bt * MIN;
    float acc[4] = {0.f, 0.f, 0.f, 0.f};
#pragma unroll
    for (int m = 0; m < MIN; m++) {
        size_t row = (size_t)s[m] * H;
        float4 v = *reinterpret_cast<const float4*>(emb + row + i4);
        acc[0] += v.x; acc[1] += v.y; acc[2] += v.z; acc[3] += v.w;
    }
    __nv_bfloat16 hv[4], lv[4];
#pragma unroll
    for (int q = 0; q < 4; q++) {
        hv[q] = __float2bfloat16(acc[q]);
        lv[q] = __float2bfloat16(acc[q] - __bfloat162float(hv[q]));
    }
    size_t o = (size_t)bt * H + i4;
    *reinterpret_cast<ull*>(&g_embx_hi[o]) = *reinterpret_cast<ull*>(hv);
    *reinterpret_cast<ull*>(&g_embx_lo[o]) = *reinterpret_cast<ull*>(lv);
}

// ---------------- split-bf16 tensor-core GEMM (now 2 CTAs/SM) ----------------
#define AS_STRIDE 40
#define BS_STRIDE 136
#define AS_BUF (128 * AS_STRIDE)
#define BS_BUF (32 * BS_STRIDE)
#define OFF_AHI 0
#define OFF_ALO (2 * AS_BUF)
#define OFF_BHI (4 * AS_BUF)
#define OFF_BLO (4 * AS_BUF + 2 * BS_BUF)
#define GEMM_SMEM_BYTES (2 * (4 * AS_BUF + 4 * BS_BUF))

__global__ void __launch_bounds__(256, 2) gemm_bf16_kernel(
        const __nv_bfloat16* __restrict__ Ahi, const __nv_bfloat16* __restrict__ Alo,
        const __nv_bfloat16* __restrict__ Bhi, const __nv_bfloat16* __restrict__ Blo,
        const float* __restrict__ bias, float* __restrict__ C,
        int Mr, int N, int K) {
    extern __shared__ __nv_bfloat16 smem_bf[];
    const uint32_t sbase = (uint32_t)__cvta_generic_to_shared(smem_bf);
    const int tid  = threadIdx.x;
    const int lane = tid & 31;
    const int wid  = tid >> 5;
    const int m0 = blockIdx.y * 128;
    const int n0 = blockIdx.x * 128;
    const int wm = (wid & 3) * 32;
    const int wn = (wid >> 2) * 64;

    int aRow[2], aCol[2], bRow[2], bCol[2];
    bool aOk[2];
#pragma unroll
    for (int l = 0; l < 2; l++) {
        int c = tid + l * 256;
        aRow[l] = c >> 2;  aCol[l] = (c & 3) * 8;
        bRow[l] = c >> 4;  bCol[l] = (c & 15) * 8;
        aOk[l] = (m0 + aRow[l]) < Mr;
    }

#define ISSUE_STAGE(KT, P) do {                                                   \
    _Pragma("unroll")                                                             \
    for (int l = 0; l < 2; l++) {                                                 \
        if (aOk[l]) {                                                             \
            size_t go = (size_t)(m0 + aRow[l]) * K + (KT) + aCol[l];              \
            uint32_t so = (uint32_t)((P) * AS_BUF + aRow[l] * AS_STRIDE + aCol[l]); \
            cp16(sbase + 2u * (OFF_AHI + so), Ahi + go);                          \
            cp16(sbase + 2u * (OFF_ALO + so), Alo + go);                          \
        }                                                                         \
        {                                                                         \
            size_t go = (size_t)((KT) + bRow[l]) * N + n0 + bCol[l];              \
            uint32_t so = (uint32_t)((P) * BS_BUF + bRow[l] * BS_STRIDE + bCol[l]); \
            cp16(sbase + 2u * (OFF_BHI + so), Bhi + go);                          \
            cp16(sbase + 2u * (OFF_BLO + so), Blo + go);                          \
        }                                                                         \
    }                                                                             \
    cp_commit();                                                                  \
} while (0)

    float cfr[2][8][4];
#pragma unroll
    for (int i = 0; i < 2; i++)
#pragma unroll
        for (int j = 0; j < 8; j++)
#pragma unroll
            for (int q = 0; q < 4; q++) cfr[i][j][q] = 0.f;

    ISSUE_STAGE(0, 0);
    int p = 0;
    for (int kt = 0; kt < K; kt += 32) {
        const bool more = (kt + 32) < K;
        if (more) { ISSUE_STAGE(kt + 32, p ^ 1); cp_wait<1>(); }
        else      { cp_wait<0>(); }
        __syncthreads();

#pragma unroll
        for (int kk = 0; kk < 2; kk++) {
            uint32_t ah[2][4], al[2][4];
#pragma unroll
            for (int i = 0; i < 2; i++) {
                int r  = wm + i * 16 + (lane & 15);
                int cc = kk * 16 + ((lane >> 4) << 3);
                uint32_t ao = (uint32_t)(p * AS_BUF + r * AS_STRIDE + cc);
                ldm_x4(ah[i], sbase + 2u * (OFF_AHI + ao));
                ldm_x4(al[i], sbase + 2u * (OFF_ALO + ao));
            }
            uint32_t bh[4][4], bl[4][4];
#pragma unroll
            for (int j2 = 0; j2 < 4; j2++) {
                int kr = kk * 16 + (lane & 15);
                int nc = wn + j2 * 16 + ((lane >> 4) << 3);
                uint32_t bo = (uint32_t)(p * BS_BUF + kr * BS_STRIDE + nc);
                ldm_x4_t(bh[j2], sbase + 2u * (OFF_BHI + bo));
                ldm_x4_t(bl[j2], sbase + 2u * (OFF_BLO + bo));
            }
#pragma unroll
            for (int i = 0; i < 2; i++)
#pragma unroll
                for (int j = 0; j < 8; j++) {
                    const uint32_t* bhp = &bh[j >> 1][(j & 1) * 2];
                    const uint32_t* blp = &bl[j >> 1][(j & 1) * 2];
                    mma_bf16(cfr[i][j], ah[i], bhp);
                    mma_bf16(cfr[i][j], ah[i], blp);
                    mma_bf16(cfr[i][j], al[i], bhp);
                }
        }
        __syncthreads();
        p ^= 1;
    }

    const int rbase = m0 + wm + (lane >> 2);
    const int cbase = n0 + wn + (lane & 3) * 2;
#pragma unroll
    for (int i = 0; i < 2; i++) {
#pragma unroll
        for (int j = 0; j < 8; j++) {
            int col  = cbase + j * 8;
            float2 bv = *reinterpret_cast<const float2*>(&bias[col]);
            int row0 = rbase + i * 16;
            int row1 = row0 + 8;
            if (row0 < Mr) {
                float2 v = make_float2(cfr[i][j][0] + bv.x, cfr[i][j][1] + bv.y);
                *reinterpret_cast<float2*>(&C[(size_t)row0 * N + col]) = v;
            }
            if (row1 < Mr) {
                float2 v = make_float2(cfr[i][j][2] + bv.x, cfr[i][j][3] + bv.y);
                *reinterpret_cast<float2*>(&C[(size_t)row1 * N + col]) = v;
            }
        }
    }
#undef ISSUE_STAGE
}

// ---------------- persistent bidirectional GRU (R13/R15, FROZEN) ------------
__global__ void __launch_bounds__(256, 1) gru_kernel(
        const float* __restrict__ Wh_f, const float* __restrict__ brec_f,
        const float* __restrict__ Wh_b, const float* __restrict__ brec_b) {
    extern __shared__ float sm[];
    float* h_s = sm;              // [B][H] 64KB
    float* W_s = sm + B * H;      // [3*JS][H] 48KB

    const int dir = blockIdx.x >> 6;
    const int jb  = blockIdx.x & (NB - 1);
    const int j0  = jb * JS;
    const int tid = threadIdx.x;
    const int kq  = tid & 7;
    const int bq  = (tid >> 3) & 7;
    const int jj  = tid >> 6;
    const int bown = bq * 4 + kq;      // batch this lane finalizes (kq<4)

    const float* Wh   = dir ? Wh_b   : Wh_f;
    const float* brec = dir ? brec_b : brec_f;
    const float* gx   = g_gx + dir * H3;   // row stride H6

    for (int idx = tid; idx < 3 * JS * H; idx += 256) {
        int k = idx / (3 * JS);
        int r = idx - k * (3 * JS);
        int g = r >> 3;
        int c = r & 7;
        W_s[(g * JS + c) * H + k] = Wh[(size_t)k * H3 + g * H + j0 + c];
    }
    float2 brg[3];
#pragma unroll
    for (int g = 0; g < 3; g++)
        brg[g] = *reinterpret_cast<const float2*>(brec + g * H + j0 + jj * 2);
    __syncthreads();

    float* hbuf0 = g_hbuf[dir][0];
    float* hbuf1 = g_hbuf[dir][1];
    volatile unsigned* bar = &g_bar[dir];

    int soff[4];
#pragma unroll
    for (int pp = 0; pp < 4; pp++) {
        int idx = tid * 4 + pp * 1024;
        soff[pp] = (idx >> 7) * H + (idx & 127);
    }
    uint32_t hs_base = (uint32_t)__cvta_generic_to_shared(h_s);

    for (int s = 0; s < T; s++) {
        const int t = dir ? (T - 1 - s) : s;
        const float* hin  = (s & 1) ? hbuf1 : hbuf0;
        float*       hout = (s & 1) ? hbuf0 : hbuf1;

        // stage h in 4 cp.async groups (16KB each)
#pragma unroll
        for (int c = 0; c < 4; c++) {
#pragma unroll
            for (int pp = 0; pp < 4; pp++)
                cp16(hs_base + (soff[pp] + c * 128) * 4, hin + soff[pp] + c * 128);
            cp_commit();
        }

        // gx prefetch: lane kq<4 loads only its own batch
        float2 gxv[3];
        if (kq < 4) {
            size_t gb = ((size_t)bown * T + t) * H6 + j0 + jj * 2;
            gxv[0] = *reinterpret_cast<const float2*>(gx + gb);
            gxv[1] = *reinterpret_cast<const float2*>(gx + gb + H);
            gxv[2] = *reinterpret_cast<const float2*>(gx + gb + 2 * H);
        }

        ull acc[3][2][4];
#pragma unroll
        for (int g = 0; g < 3; g++)
#pragma unroll
            for (int a = 0; a < 2; a++)
#pragma unroll
                for (int c = 0; c < 4; c++) acc[g][a][c] = 0ull;

        const int kbase = kq * 4;
#pragma unroll
        for (int qc = 0; qc < 4; qc++) {
            if (qc == 0) cp_wait<3>();
            else if (qc == 1) cp_wait<2>();
            else if (qc == 2) cp_wait<1>();
            else cp_wait<0>();
            __syncthreads();
#pragma unroll
            for (int i = qc * 4; i < qc * 4 + 4; i++) {
                const int k = kbase + i * 32;
                ulonglong2 w[3][2];
#pragma unroll
                for (int g = 0; g < 3; g++)
#pragma unroll
                    for (int jj2 = 0; jj2 < 2; jj2++)
                        w[g][jj2] = *reinterpret_cast<const ulonglong2*>(
                            &W_s[(g * JS + jj * 2 + jj2) * H + k]);
                ulonglong2 hv[4];
#pragma unroll
                for (int bi = 0; bi < 4; bi++)
                    hv[bi] = *reinterpret_cast<const ulonglong2*>(&h_s[(bq * 4 + bi) * H + k]);
#pragma unroll
                for (int g = 0; g < 3; g++)
#pragma unroll
                    for (int jj2 = 0; jj2 < 2; jj2++)
#pragma unroll
                        for (int bi = 0; bi < 4; bi++) {
                            acc[g][jj2][bi] = fma2(hv[bi].x, w[g][jj2].x, acc[g][jj2][bi]);
                            acc[g][jj2][bi] = fma2(hv[bi].y, w[g][jj2].y, acc[g][jj2][bi]);
                        }
            }
        }

        // pair-sum + reduce over kq lanes (bits 0..2)
        float red[3][2][4];
#pragma unroll
        for (int g = 0; g < 3; g++)
#pragma unroll
            for (int jj2 = 0; jj2 < 2; jj2++)
#pragma unroll
                for (int bi = 0; bi < 4; bi++) {
                    float x = lo2(acc[g][jj2][bi]) + hi2(acc[g][jj2][bi]);
                    x += __shfl_xor_sync(0xffffffffu, x, 1);
                    x += __shfl_xor_sync(0xffffffffu, x, 2);
                    x += __shfl_xor_sync(0xffffffffu, x, 4);
                    red[g][jj2][bi] = x;
                }

        // finalize: lane kq=c handles batch bown (c<4)
        unsigned hi_pack = 0, lo_pack = 0;
        if (kq < 4) {
            const float2 hp = *reinterpret_cast<const float2*>(&h_s[bown * H + j0 + jj * 2]);
            float hn[2];
#pragma unroll
            for (int jj2 = 0; jj2 < 2; jj2++) {
                const float az = red[0][jj2][kq] + ((jj2) ? brg[0].y : brg[0].x);
                const float ar = red[1][jj2][kq] + ((jj2) ? brg[1].y : brg[1].x);
                const float an = red[2][jj2][kq] + ((jj2) ? brg[2].y : brg[2].x);
                const float xz = (jj2) ? gxv[0].y : gxv[0].x;
                const float xr = (jj2) ? gxv[1].y : gxv[1].x;
                const float xn = (jj2) ? gxv[2].y : gxv[2].x;
                const float hprev = (jj2) ? hp.y : hp.x;
                const float zg = 1.f / (1.f + expf(-(xz + az)));
                const float rg = 1.f / (1.f + expf(-(xr + ar)));
                const float hc = tanhf(xn + rg * an);
                hn[jj2] = zg * hprev + (1.f - zg) * hc;
            }
            asm volatile("st.global.cg.v2.f32 [%0], {%1, %2};"
                         :: "l"(hout + bown * H + j0 + jj * 2), "f"(hn[0]), "f"(hn[1]));
            __nv_bfloat16 h0 = __float2bfloat16(hn[0]);
            __nv_bfloat16 h1 = __float2bfloat16(hn[1]);
            __nv_bfloat16 l0 = __float2bfloat16(hn[0] - __bfloat162float(h0));
            __nv_bfloat16 l1 = __float2bfloat16(hn[1] - __bfloat162float(h1));
            hi_pack = (unsigned)*reinterpret_cast<unsigned short*>(&h0)
                    | ((unsigned)*reinterpret_cast<unsigned short*>(&h1) << 16);
            lo_pack = (unsigned)*reinterpret_cast<unsigned short*>(&l0)
                    | ((unsigned)*reinterpret_cast<unsigned short*>(&l1) << 16);
        }

        // arrive early: h published; outcat happens while others arrive
        __syncthreads();
        if (tid == 0) {
            __threadfence();
            atomicAdd((unsigned*)bar, 1u);
        }

        // outcat split-bf16 store (+ final h rows BT..)
        if (kq < 4) {
            size_t o = ((size_t)bown * T + t) * H2 + dir * H + j0 + jj * 2;
            *reinterpret_cast<unsigned*>(&g_oc_hi[o]) = hi_pack;
            *reinterpret_cast<unsigned*>(&g_oc_lo[o]) = lo_pack;
            if (s == T - 1) {
                size_t o2 = ((size_t)(BT + bown)) * H2 + dir * H + j0 + jj * 2;
                *reinterpret_cast<unsigned*>(&g_oc_hi[o2]) = hi_pack;
                *reinterpret_cast<unsigned*>(&g_oc_lo[o2]) = lo_pack;
            }
        }

        // wait: tid0-only direct spin on the single counter (FROZEN pattern)
        if (tid == 0) {
            const unsigned target = (unsigned)(NB * (s + 1));
            while (*bar < target) {}
            __threadfence();
        }
        __syncthreads();
    }
}

// ---------------- launch ----------------
extern "C" void kernel_launch(void* const* d_in, const int* in_sizes, int n_in,
                              void* d_out, int out_size) {
    (void)in_sizes; (void)n_in; (void)out_size;
    const int*   seqs = (const int*)d_in[0];
    const float* emb  = (const float*)d_in[2];
    const float* Wx_f = (const float*)d_in[3];
    const float* Wh_f = (const float*)d_in[4];
    const float* b_f  = (const float*)d_in[5];
    const float* Wx_b = (const float*)d_in[6];
    const float* Wh_b = (const float*)d_in[7];
    const float* b_b  = (const float*)d_in[8];
    const float* Wd   = (const float*)d_in[9];
    const float* bd   = (const float*)d_in[10];
    float* out = (float*)d_out;

    const int smem_gru = (B * H + 3 * JS * H) * (int)sizeof(float); // 112 KB
    cudaFuncSetAttribute(gru_kernel, cudaFuncAttributeMaxDynamicSharedMemorySize, smem_gru);
    cudaFuncSetAttribute(gemm_bf16_kernel, cudaFuncAttributeMaxDynamicSharedMemorySize, GEMM_SMEM_BYTES);

    __nv_bfloat16 *p_exh, *p_exl, *p_wch, *p_wcl, *p_wdh, *p_wdl, *p_och, *p_ocl;
    float *p_gx, *p_bcat;
    cudaGetSymbolAddress((void**)&p_exh, g_embx_hi);
    cudaGetSymbolAddress((void**)&p_exl, g_embx_lo);
    cudaGetSymbolAddress((void**)&p_wch, g_wxc_hi);
    cudaGetSymbolAddress((void**)&p_wcl, g_wxc_lo);
    cudaGetSymbolAddress((void**)&p_wdh, g_wd_hi);
    cudaGetSymbolAddress((void**)&p_wdl, g_wd_lo);
    cudaGetSymbolAddress((void**)&p_och, g_oc_hi);
    cudaGetSymbolAddress((void**)&p_ocl, g_oc_lo);
    cudaGetSymbolAddress((void**)&p_gx,  g_gx);
    cudaGetSymbolAddress((void**)&p_bcat, g_bcat);

    init_kernel<<<64, 256>>>();
    embed_kernel<<<BT, 128>>>(seqs, emb);

    split_cat_kernel<<<(H * H3 + 255) / 256, 256>>>(Wx_f, p_wch, p_wcl, H, H3, H6, 0);
    split_cat_kernel<<<(H * H3 + 255) / 256, 256>>>(Wx_b, p_wch, p_wcl, H, H3, H6, H3);
    split_kernel<<<(H2 * H + 255) / 256, 256>>>(Wd, p_wdh, p_wdl, H2 * H);
    bias_cat_kernel<<<(H3 + 255) / 256, 256>>>(b_f, b_b);

    // single merged gx GEMM: [BT,512] @ [512,3072] + bcat
    gemm_bf16_kernel<<<dim3(H6 / 128, BT / 128), 256, GEMM_SMEM_BYTES>>>(
        p_exh, p_exl, p_wch, p_wcl, p_bcat, p_gx, BT, H6, H);

    gru_kernel<<<2 * NB, 256, smem_gru>>>(Wh_f, b_f + H3, Wh_b, b_b + H3);

    // merged projection: rows 0..BT-1 outputs, BT..BT+B-1 hidden
    gemm_bf16_kernel<<<dim3(H / 128, (BT + B + 127) / 128), 256, GEMM_SMEM_BYTES>>>(
        p_och, p_ocl, p_wdh, p_wdl, bd, out, BT + B, H, H2);
}